// round 16
// baseline (speedup 1.0000x reference)
#include <cuda_runtime.h>

// Row-wise normalization: out[r, :] = in[r, :] / sum(in[r, :])
// Rows = 2*32*1024 = 65536, row length = 1024 floats = 256 float4.
//
// Flat grid, TWO warps per row, 4 float4 per lane — but ONE block-wide
// __syncthreads instead of 4 named barriers. Named barriers consume one of
// the SM's 16 HW barrier slots per ID: 4 IDs/block capped residency at
// ~4 blocks/SM (achieved occ ~38% in R9-R11 despite 8-block reg budget).
// A single __syncthreads restores 8 blocks/SM. Loads are front-batched in
// every warp before the barrier, so block-wide coupling costs only the
// spread among 8 same-phase warps.
__global__ void __launch_bounds__(256, 8)
normalizer_kernel(const float4* __restrict__ in, float4* __restrict__ out) {
    const unsigned tid  = threadIdx.x;
    const unsigned w    = tid >> 5;          // warp 0..7
    const unsigned lane = tid & 31u;
    const unsigned pair = w >> 1;            // row within block 0..3
    const unsigned half = w & 1u;            // which half of the row
    const unsigned row  = blockIdx.x * 4u + pair;

    const size_t base = (size_t)row * 256u + half * 128u + lane;
    const float4* __restrict__ rp = in  + base;
    float4*       __restrict__ wp = out + base;

    float4 v[4];
    #pragma unroll
    for (int k = 0; k < 4; k++)
        v[k] = __ldcs(rp + 32 * k);          // 4 independent LDG.128

    float s = 0.0f;
    #pragma unroll
    for (int k = 0; k < 4; k++)
        s += (v[k].x + v[k].y) + (v[k].z + v[k].w);

    #pragma unroll
    for (int off = 16; off > 0; off >>= 1)
        s += __shfl_xor_sync(0xffffffffu, s, off);

    // Cross-warp exchange: single block-wide barrier (1 HW barrier slot)
    __shared__ float part[8];
    if (lane == 0) part[w] = s;
    __syncthreads();
    const float deg = part[pair * 2] + part[pair * 2 + 1];

    float inv = 1.0f / deg;
    if (!isfinite(inv)) inv = 0.0f;          // reference: remove_nan_inf

    #pragma unroll
    for (int k = 0; k < 4; k++) {
        float4 t = v[k];
        t.x *= inv; t.y *= inv; t.z *= inv; t.w *= inv;
        __stcs(wp + 32 * k, t);
    }
}

extern "C" void kernel_launch(void* const* d_in, const int* in_sizes, int n_in,
                              void* d_out, int out_size) {
    (void)in_sizes; (void)n_in; (void)out_size;
    const float4* in  = (const float4*)d_in[0];
    float4*       out = (float4*)d_out;

    // 65536 rows, 4 rows per block -> 16384 blocks
    normalizer_kernel<<<65536 / 4, 256>>>(in, out);
}